// round 5
// baseline (speedup 1.0000x reference)
#include <cuda_runtime.h>
#include <math.h>

#define A_N 8192
#define K_N 64
#define D_N 128
#define B_N 16384
#define GRID_N (A_N + B_N / 4)

// Scratch: per-anchor npair losses [0, A_N) and per-row norms [A_N, A_N+B_N).
__device__ float g_part[A_N + B_N];
// Completion counter for last-block final reduction (reset each launch by last block).
__device__ unsigned int g_count;

__device__ __forceinline__ int load_idx(const void* p, long long i, int is64) {
    return is64 ? (int)((const long long*)p)[i] : ((const int*)p)[i];
}

// Merge two multi-dot partial registers at lane-distance s:
// 1 shuffle + selects instead of 2 full butterflies.
__device__ __forceinline__ float merge2(float x, float y, int s, int lane) {
    float send = (lane & s) ? x : y;
    float keep = (lane & s) ? y : x;
    float t = __shfl_xor_sync(0xffffffffu, send, s);
    return keep + t;
}

// ---------------------------------------------------------------------------
// Single fused kernel:
//   blocks [0, A_N): one block (4 warps) per anchor -> N-pair loss term.
//   blocks [A_N, GRID_N): per-row L2 norms, 4 rows per block.
//   last block to finish: deterministic final reduction -> out[0].
// Index dtype (int32 vs int64) detected per-warp from the block's own slice of
// neg_ind: indices < 16384, so under little-endian int64 all odd 32-bit words
// are zero; under int32 they are random indices (P(all 32 zero) ~ 1e-135).
// ---------------------------------------------------------------------------
__global__ __launch_bounds__(128) void fused_kernel(
    const float* __restrict__ E,
    const void* __restrict__ anc,
    const void* __restrict__ pos,
    const void* __restrict__ neg,
    float* __restrict__ out)
{
    const int t = threadIdx.x;
    const int w = t >> 5;
    const int l = t & 31;

    __shared__ float sA[D_N];
    __shared__ float sRed[4];
    __shared__ float sM[4], sS[4];
    __shared__ unsigned int sLast;

    if (blockIdx.x >= A_N) {
        // ---- L2 norms: one warp per row; route stores through thread 0 ----
        const int row = (blockIdx.x - A_N) * 4 + w;
        const float4 v = ((const float4*)(E + (long long)row * D_N))[l];
        float s = v.x * v.x + v.y * v.y + v.z * v.z + v.w * v.w;
        #pragma unroll
        for (int o = 16; o; o >>= 1) s += __shfl_xor_sync(0xffffffffu, s, o);
        if (l == 0) sRed[w] = sqrtf(s);
        __syncthreads();
        if (t == 0) {
            const int rb = A_N + (blockIdx.x - A_N) * 4;
            g_part[rb + 0] = sRed[0];
            g_part[rb + 1] = sRed[1];
            g_part[rb + 2] = sRed[2];
            g_part[rb + 3] = sRed[3];
        }
    } else {
        const int a = blockIdx.x;

        // ---- per-warp dtype detection (1 LDG + 5 shuffles) ----
        unsigned int det = ((const unsigned int*)neg)[a * 64 + 2 * l + 1];
        #pragma unroll
        for (int o = 16; o; o >>= 1) det |= __shfl_xor_sync(0xffffffffu, det, o);
        const int is64 = (det == 0u) ? 1 : 0;

        const int ai = load_idx(anc, a, is64);
        const int pi = load_idx(pos, a, is64);

        const float av = E[(long long)ai * D_N + t];
        const float pv = E[(long long)pi * D_N + t];
        sA[t] = av;

        // Block-reduce a.p (computed once, subtracted as a scalar)
        float ap = av * pv;
        #pragma unroll
        for (int o = 16; o; o >>= 1) ap += __shfl_xor_sync(0xffffffffu, ap, o);
        if (l == 0) sRed[w] = ap;
        __syncthreads();
        const float apf = sRed[0] + sRed[1] + sRed[2] + sRed[3];

        const float4 a4 = ((const float4*)sA)[l];

        // ---- 16 negatives per warp; coalesced float4 gathers, front-batched ----
        const long long kbase = (long long)a * K_N + (long long)w * 16;
        float d[16];
        #pragma unroll
        for (int j = 0; j < 16; j++) {
            const long long nidx = (long long)load_idx(neg, kbase + j, is64);
            const float4 v = __ldg((const float4*)(E + nidx * D_N) + l);
            d[j] = v.x * a4.x + v.y * a4.y + v.z * a4.z + v.w * a4.w;
        }

        // ---- merge-tree reduce: 16 dots x 32 lanes in 16 shuffles ----
        float e[8], f[4], g[2], h;
        #pragma unroll
        for (int m = 0; m < 8; m++) e[m] = merge2(d[2 * m], d[2 * m + 1], 16, l);
        #pragma unroll
        for (int m = 0; m < 4; m++) f[m] = merge2(e[2 * m], e[2 * m + 1], 8, l);
        #pragma unroll
        for (int m = 0; m < 2; m++) g[m] = merge2(f[2 * m], f[2 * m + 1], 4, l);
        h = merge2(g[0], g[1], 2, l);
        h += __shfl_xor_sync(0xffffffffu, h, 1);
        const float inner = h - apf;  // lane l holds dot k(l), duplicated x2

        // ---- in-warp logsumexp over this warp's 16 dots ----
        float m1 = inner;
        #pragma unroll
        for (int o = 16; o; o >>= 1) m1 = fmaxf(m1, __shfl_xor_sync(0xffffffffu, m1, o));
        float s1 = __expf(inner - m1);
        #pragma unroll
        for (int o = 16; o; o >>= 1) s1 += __shfl_xor_sync(0xffffffffu, s1, o);
        if (l == 0) { sM[w] = m1; sS[w] = 0.5f * s1; }  // halve: duplicates
        __syncthreads();

        if (t == 0) {
            float M = fmaxf(fmaxf(sM[0], sM[1]), fmaxf(sM[2], sM[3]));
            float S = sS[0] * __expf(sM[0] - M) + sS[1] * __expf(sM[1] - M)
                    + sS[2] * __expf(sM[2] - M) + sS[3] * __expf(sM[3] - M);
            const float lse = M + logf(S);
            g_part[a] = fmaxf(lse, 0.0f) + log1pf(expf(-fabsf(lse)));
        }
    }

    // ---- completion handshake: last block does the final reduction ----
    __syncthreads();
    if (t == 0) {
        __threadfence();  // make this block's g_part writes globally visible
        const unsigned int old = atomicAdd(&g_count, 1u);
        sLast = (old == (unsigned int)(GRID_N - 1)) ? 1u : 0u;
    }
    __syncthreads();
    if (sLast) {
        __threadfence();  // acquire: see all other blocks' g_part writes
        const float invA = 1.0f / (float)A_N;
        const float cB   = 0.25f / (float)B_N;
        const float4* __restrict__ p4 = (const float4*)g_part;
        float accA = 0.0f, accB = 0.0f;
        #pragma unroll 4
        for (int i = t; i < A_N / 4; i += 128) {
            const float4 v = p4[i];
            accA += (v.x + v.y) + (v.z + v.w);
        }
        #pragma unroll 4
        for (int i = A_N / 4 + t; i < (A_N + B_N) / 4; i += 128) {
            const float4 v = p4[i];
            accB += (v.x + v.y) + (v.z + v.w);
        }
        float acc = accA * invA + accB * cB;
        #pragma unroll
        for (int o = 16; o; o >>= 1) acc += __shfl_xor_sync(0xffffffffu, acc, o);
        if (l == 0) sRed[w] = acc;
        __syncthreads();
        if (t == 0) {
            out[0] = sRed[0] + sRed[1] + sRed[2] + sRed[3];
            g_count = 0u;  // reset for next graph replay
        }
    }
}

extern "C" void kernel_launch(void* const* d_in, const int* in_sizes, int n_in,
                              void* d_out, int out_size) {
    const float* E   = (const float*)d_in[0];   // image_embed [B, D] f32
    const void*  anc = d_in[1];                 // anc_ind [A]
    const void*  pos = d_in[2];                 // pos_ind [A]
    const void*  neg = d_in[3];                 // neg_ind [A, K]
    float* out = (float*)d_out;

    fused_kernel<<<GRID_N, 128>>>(E, anc, pos, neg, out);
}

// round 6
// speedup vs baseline: 1.0097x; 1.0097x over previous
#include <cuda_runtime.h>
#include <math.h>

#define A_N 8192
#define K_N 64
#define D_N 128
#define B_N 16384
#define GRID_N (A_N + B_N / 4)

// Scratch: per-anchor npair losses [0, A_N) and per-row norms [A_N, A_N+B_N).
__device__ float g_part[A_N + B_N];
// Completion counter for last-block final reduction (reset each launch by last block).
__device__ unsigned int g_count;

__device__ __forceinline__ int load_idx(const void* p, long long i, int is64) {
    return is64 ? (int)((const long long*)p)[i] : ((const int*)p)[i];
}

// Merge two multi-dot partial registers at lane-distance s:
// 1 shuffle + selects instead of 2 full butterflies.
__device__ __forceinline__ float merge2(float x, float y, int s, int lane) {
    float send = (lane & s) ? x : y;
    float keep = (lane & s) ? y : x;
    float t = __shfl_xor_sync(0xffffffffu, send, s);
    return keep + t;
}

// Release+acquire atomic increment at gpu scope. Release orders this block's
// prior global stores; crucially this does NOT emit CCTL.IVALL (no L1D flush),
// unlike __threadfence() which invalidates L1 for all co-resident CTAs.
__device__ __forceinline__ unsigned int atom_inc_acq_rel(unsigned int* p) {
    unsigned int old;
    asm volatile("atom.acq_rel.gpu.global.add.u32 %0, [%1], %2;"
                 : "=r"(old) : "l"(p), "r"(1u) : "memory");
    return old;
}

// Cache-bypassing float4 load (always fresh from L2) for the final reduction;
// avoids needing any acquire fence / L1 invalidate on the reader side.
__device__ __forceinline__ float4 ldcv4(const float4* p) {
    float4 v;
    asm volatile("ld.global.cv.v4.f32 {%0,%1,%2,%3}, [%4];"
                 : "=f"(v.x), "=f"(v.y), "=f"(v.z), "=f"(v.w)
                 : "l"(p) : "memory");
    return v;
}

// ---------------------------------------------------------------------------
// Single fused kernel:
//   blocks [0, A_N): one block (4 warps) per anchor -> N-pair loss term.
//   blocks [A_N, GRID_N): per-row L2 norms, 4 rows per block.
//   last block to finish: deterministic final reduction -> out[0].
// Index dtype (int32 vs int64) detected per-warp from the block's own slice of
// neg_ind: indices < 16384, so under little-endian int64 all odd 32-bit words
// are zero; under int32 they are random indices (P(all 32 zero) ~ 1e-135).
// ---------------------------------------------------------------------------
__global__ __launch_bounds__(128) void fused_kernel(
    const float* __restrict__ E,
    const void* __restrict__ anc,
    const void* __restrict__ pos,
    const void* __restrict__ neg,
    float* __restrict__ out)
{
    const int t = threadIdx.x;
    const int w = t >> 5;
    const int l = t & 31;

    __shared__ float sA[D_N];
    __shared__ float sRed[4];
    __shared__ float sM[4], sS[4];
    __shared__ unsigned int sLast;

    if (blockIdx.x >= A_N) {
        // ---- L2 norms: one warp per row ----
        const int row = (blockIdx.x - A_N) * 4 + w;
        const float4 v = ((const float4*)(E + (long long)row * D_N))[l];
        float s = v.x * v.x + v.y * v.y + v.z * v.z + v.w * v.w;
        #pragma unroll
        for (int o = 16; o; o >>= 1) s += __shfl_xor_sync(0xffffffffu, s, o);
        if (l == 0) sRed[w] = sqrtf(s);
        __syncthreads();
        if (t == 0) {
            const int rb = A_N + (blockIdx.x - A_N) * 4;
            g_part[rb + 0] = sRed[0];
            g_part[rb + 1] = sRed[1];
            g_part[rb + 2] = sRed[2];
            g_part[rb + 3] = sRed[3];
        }
    } else {
        const int a = blockIdx.x;

        // ---- per-warp dtype detection (1 LDG + 5 shuffles) ----
        unsigned int det = ((const unsigned int*)neg)[a * 64 + 2 * l + 1];
        #pragma unroll
        for (int o = 16; o; o >>= 1) det |= __shfl_xor_sync(0xffffffffu, det, o);
        const int is64 = (det == 0u) ? 1 : 0;

        const int ai = load_idx(anc, a, is64);
        const int pi = load_idx(pos, a, is64);

        const float av = E[(long long)ai * D_N + t];
        const float pv = E[(long long)pi * D_N + t];
        sA[t] = av;

        // Block-reduce a.p (computed once, subtracted as a scalar)
        float ap = av * pv;
        #pragma unroll
        for (int o = 16; o; o >>= 1) ap += __shfl_xor_sync(0xffffffffu, ap, o);
        if (l == 0) sRed[w] = ap;
        __syncthreads();
        const float apf = sRed[0] + sRed[1] + sRed[2] + sRed[3];

        const float4 a4 = ((const float4*)sA)[l];

        // ---- 16 negatives per warp; coalesced float4 gathers, front-batched ----
        const long long kbase = (long long)a * K_N + (long long)w * 16;
        float d[16];
        #pragma unroll
        for (int j = 0; j < 16; j++) {
            const long long nidx = (long long)load_idx(neg, kbase + j, is64);
            const float4 v = __ldg((const float4*)(E + nidx * D_N) + l);
            d[j] = v.x * a4.x + v.y * a4.y + v.z * a4.z + v.w * a4.w;
        }

        // ---- merge-tree reduce: 16 dots x 32 lanes in 16 shuffles ----
        float e[8], f[4], g[2], h;
        #pragma unroll
        for (int m = 0; m < 8; m++) e[m] = merge2(d[2 * m], d[2 * m + 1], 16, l);
        #pragma unroll
        for (int m = 0; m < 4; m++) f[m] = merge2(e[2 * m], e[2 * m + 1], 8, l);
        #pragma unroll
        for (int m = 0; m < 2; m++) g[m] = merge2(f[2 * m], f[2 * m + 1], 4, l);
        h = merge2(g[0], g[1], 2, l);
        h += __shfl_xor_sync(0xffffffffu, h, 1);
        const float inner = h - apf;  // lane l holds dot k(l), duplicated x2

        // ---- in-warp logsumexp over this warp's 16 dots ----
        float m1 = inner;
        #pragma unroll
        for (int o = 16; o; o >>= 1) m1 = fmaxf(m1, __shfl_xor_sync(0xffffffffu, m1, o));
        float s1 = __expf(inner - m1);
        #pragma unroll
        for (int o = 16; o; o >>= 1) s1 += __shfl_xor_sync(0xffffffffu, s1, o);
        if (l == 0) { sM[w] = m1; sS[w] = 0.5f * s1; }  // halve: duplicates
        __syncthreads();

        if (t == 0) {
            float M = fmaxf(fmaxf(sM[0], sM[1]), fmaxf(sM[2], sM[3]));
            float S = sS[0] * __expf(sM[0] - M) + sS[1] * __expf(sM[1] - M)
                    + sS[2] * __expf(sM[2] - M) + sS[3] * __expf(sM[3] - M);
            const float lse = M + logf(S);
            g_part[a] = fmaxf(lse, 0.0f) + log1pf(expf(-fabsf(lse)));
        }
    }

    // ---- completion handshake (NO __threadfence -> no L1D flush) ----
    __syncthreads();
    if (t == 0) {
        const unsigned int old = atom_inc_acq_rel(&g_count);
        sLast = (old == (unsigned int)(GRID_N - 1)) ? 1u : 0u;
    }
    __syncthreads();
    if (sLast) {
        // Reader side: .cv loads bypass L1, so no acquire fence needed.
        const float invA = 1.0f / (float)A_N;
        const float cB   = 0.25f / (float)B_N;
        const float4* p4 = (const float4*)g_part;
        float accA = 0.0f, accB = 0.0f;
        #pragma unroll 4
        for (int i = t; i < A_N / 4; i += 128) {
            const float4 v = ldcv4(p4 + i);
            accA += (v.x + v.y) + (v.z + v.w);
        }
        #pragma unroll 4
        for (int i = A_N / 4 + t; i < (A_N + B_N) / 4; i += 128) {
            const float4 v = ldcv4(p4 + i);
            accB += (v.x + v.y) + (v.z + v.w);
        }
        float acc = accA * invA + accB * cB;
        #pragma unroll
        for (int o = 16; o; o >>= 1) acc += __shfl_xor_sync(0xffffffffu, acc, o);
        if (l == 0) sRed[w] = acc;
        __syncthreads();
        if (t == 0) {
            out[0] = sRed[0] + sRed[1] + sRed[2] + sRed[3];
            g_count = 0u;  // reset for next graph replay
        }
    }
}

extern "C" void kernel_launch(void* const* d_in, const int* in_sizes, int n_in,
                              void* d_out, int out_size) {
    const float* E   = (const float*)d_in[0];   // image_embed [B, D] f32
    const void*  anc = d_in[1];                 // anc_ind [A]
    const void*  pos = d_in[2];                 // pos_ind [A]
    const void*  neg = d_in[3];                 // neg_ind [A, K]
    float* out = (float*)d_out;

    fused_kernel<<<GRID_N, 128>>>(E, anc, pos, neg, out);
}